// round 3
// baseline (speedup 1.0000x reference)
#include <cuda_runtime.h>
#include <cstdint>

// Problem constants
#define BATCH   8192
#define INPUT   2048
#define HIDDEN  2048
#define CLASSES 10
#define KPOOL   45
#define NUM_EH  45
#define EST_DIM 270            // 45 features * 3 windows * 2 (mean,var)
#define LIN_IN  (HIDDEN + EST_DIM)   // 2318

// Scratch (device globals: allocation-free per harness rules)
__device__ float g_H[(size_t)BATCH * HIDDEN];      // tanh(x@W_ih^T + b) : 64 MB
__device__ float g_pooledT[NUM_EH * BATCH];        // pooled, transposed (f-major)
__device__ float g_cs [NUM_EH * BATCH];            // cumsum of pooled
__device__ float g_cs2[NUM_EH * BATCH];            // cumsum of pooled^2

// ---------------------------------------------------------------------------
// K1: C[b][h] = tanh( sum_i x[b][i]*W[h][i] + b_ih[h] + b_hh[h] )
// Classic SGEMM NT: 128x128 tile, BK=16, 256 threads, 8x8 per thread.
// ---------------------------------------------------------------------------
#define BM 128
#define BN 128
#define BK 16

__global__ __launch_bounds__(256) void gemm_tanh_kernel(
    const float* __restrict__ x, const float* __restrict__ W,
    const float* __restrict__ b_ih, const float* __restrict__ b_hh)
{
    __shared__ float sA[BK][BM];   // k-major
    __shared__ float sB[BK][BN];

    const int bm = blockIdx.y * BM;   // batch tile origin
    const int bn = blockIdx.x * BN;   // hidden tile origin
    const int tid = threadIdx.x;
    const int tr = tid >> 4;          // 0..15 (row group)
    const int tc = tid & 15;          // 0..15 (col group)

    float acc[8][8];
    #pragma unroll
    for (int m = 0; m < 8; m++)
        #pragma unroll
        for (int n = 0; n < 8; n++) acc[m][n] = 0.f;

    for (int k0 = 0; k0 < INPUT; k0 += BK) {
        // Load 128x16 A-tile and B-tile: 512 float4 each, 2 per thread.
        #pragma unroll
        for (int it = 0; it < 2; it++) {
            int slot = tid * 2 + it;     // 0..511
            int r = slot >> 2;           // 0..127
            int g = slot & 3;            // 0..3 (which float4 along k)
            float4 av = *(const float4*)(x + (size_t)(bm + r) * INPUT + k0 + g * 4);
            sA[g*4+0][r] = av.x; sA[g*4+1][r] = av.y;
            sA[g*4+2][r] = av.z; sA[g*4+3][r] = av.w;
            float4 wv = *(const float4*)(W + (size_t)(bn + r) * INPUT + k0 + g * 4);
            sB[g*4+0][r] = wv.x; sB[g*4+1][r] = wv.y;
            sB[g*4+2][r] = wv.z; sB[g*4+3][r] = wv.w;
        }
        __syncthreads();

        #pragma unroll
        for (int k = 0; k < BK; k++) {
            float4 a0 = *(const float4*)&sA[k][tr * 8];
            float4 a1 = *(const float4*)&sA[k][tr * 8 + 4];
            float4 b0 = *(const float4*)&sB[k][tc * 8];
            float4 b1 = *(const float4*)&sB[k][tc * 8 + 4];
            float ra[8] = {a0.x, a0.y, a0.z, a0.w, a1.x, a1.y, a1.z, a1.w};
            float rb[8] = {b0.x, b0.y, b0.z, b0.w, b1.x, b1.y, b1.z, b1.w};
            #pragma unroll
            for (int m = 0; m < 8; m++)
                #pragma unroll
                for (int n = 0; n < 8; n++)
                    acc[m][n] = fmaf(ra[m], rb[n], acc[m][n]);
        }
        __syncthreads();
    }

    // Epilogue: bias + tanh, store
    #pragma unroll
    for (int n = 0; n < 8; n++) {
        int h = bn + tc * 8 + n;
        float bias = b_ih[h] + b_hh[h];
        #pragma unroll
        for (int m = 0; m < 8; m++) {
            int row = bm + tr * 8 + m;
            g_H[(size_t)row * HIDDEN + h] = tanhf(acc[m][n] + bias);
        }
    }
}

// ---------------------------------------------------------------------------
// K2: pooled[f][b] = mean_{k<45} H[b][f*45+k], stored transposed (f-major)
// ---------------------------------------------------------------------------
__global__ __launch_bounds__(128) void pool_kernel()
{
    int b = blockIdx.x;
    __shared__ float sh[NUM_EH * KPOOL];   // 2025 floats
    const float* row = g_H + (size_t)b * HIDDEN;
    for (int i = threadIdx.x; i < NUM_EH * KPOOL; i += blockDim.x) sh[i] = row[i];
    __syncthreads();
    if (threadIdx.x < NUM_EH) {
        float s = 0.f;
        #pragma unroll
        for (int k = 0; k < KPOOL; k++) s += sh[threadIdx.x * KPOOL + k];
        g_pooledT[threadIdx.x * BATCH + b] = s * (1.0f / KPOOL);
    }
}

// ---------------------------------------------------------------------------
// K3: per-feature inclusive prefix sums of pooled and pooled^2 over batch.
// 45 blocks (one per feature), 1024 threads, 8 elements each.
// ---------------------------------------------------------------------------
__global__ __launch_bounds__(1024) void scan_kernel()
{
    int f = blockIdx.x;
    const float* p = g_pooledT + f * BATCH;
    float* cs  = g_cs  + f * BATCH;
    float* cs2 = g_cs2 + f * BATCH;
    int t = threadIdx.x;
    int base = t * 8;

    float v1[8], v2[8];
    float s1 = 0.f, s2 = 0.f;
    #pragma unroll
    for (int i = 0; i < 8; i++) {
        float xv = p[base + i];
        s1 += xv;       v1[i] = s1;
        s2 += xv * xv;  v2[i] = s2;
    }

    __shared__ float sh1[1024], sh2[1024];
    sh1[t] = s1; sh2[t] = s2;
    __syncthreads();
    for (int off = 1; off < 1024; off <<= 1) {
        float a1 = (t >= off) ? sh1[t - off] : 0.f;
        float a2 = (t >= off) ? sh2[t - off] : 0.f;
        __syncthreads();
        sh1[t] += a1; sh2[t] += a2;
        __syncthreads();
    }
    float ex1 = (t > 0) ? sh1[t - 1] : 0.f;
    float ex2 = (t > 0) ? sh2[t - 1] : 0.f;

    #pragma unroll
    for (int i = 0; i < 8; i++) {
        cs [base + i] = v1[i] + ex1;
        cs2[base + i] = v2[i] + ex2;
    }
}

// ---------------------------------------------------------------------------
// K4: per-sample: build est (270 vals) from cs/cs2, dot with W_lin, softmax.
// One block (256 threads) per sample.
// BUGFIX R2: est fill must be a strided loop — EST_DIM(270) > blockDim(256);
// previous version left s_est[256..269] as uninitialized shared memory.
// ---------------------------------------------------------------------------
__global__ __launch_bounds__(256) void final_kernel(
    const float* __restrict__ W_lin, const float* __restrict__ b_lin,
    float* __restrict__ out)
{
    int b = blockIdx.x;
    int t = threadIdx.x;
    __shared__ float s_est[EST_DIM];
    __shared__ float s_red[CLASSES][8];
    __shared__ float s_logit[CLASSES];

    for (int e = t; e < EST_DIM; e += 256) {
        int f = e / 6;
        int r = e % 6;
        int j = r >> 1;        // window index
        int isvar = r & 1;
        int L = (j == 0) ? 32 : (j == 1) ? 128 : 512;
        float cnt = fminf((float)(b + 1), (float)L);
        float c1 = g_cs [f * BATCH + b];
        float c2 = g_cs2[f * BATCH + b];
        float p1 = (b >= L) ? g_cs [f * BATCH + b - L] : 0.f;
        float p2 = (b >= L) ? g_cs2[f * BATCH + b - L] : 0.f;
        float m = (c1 - p1) / cnt;
        float var = (c2 - p2) / cnt - m * m;
        s_est[e] = isvar ? var : m;
    }
    __syncthreads();

    float acc[CLASSES];
    #pragma unroll
    for (int c = 0; c < CLASSES; c++) acc[c] = 0.f;

    const float* hrow = g_H + (size_t)b * HIDDEN;
    for (int h = t; h < HIDDEN; h += 256) {
        float v = hrow[h];
        #pragma unroll
        for (int c = 0; c < CLASSES; c++)
            acc[c] = fmaf(v, W_lin[c * LIN_IN + h], acc[c]);
    }
    for (int e = t; e < EST_DIM; e += 256) {
        float v = s_est[e];
        #pragma unroll
        for (int c = 0; c < CLASSES; c++)
            acc[c] = fmaf(v, W_lin[c * LIN_IN + HIDDEN + e], acc[c]);
    }

    // block reduce (10 values)
    #pragma unroll
    for (int c = 0; c < CLASSES; c++) {
        float v = acc[c];
        #pragma unroll
        for (int off = 16; off; off >>= 1)
            v += __shfl_down_sync(0xffffffffu, v, off);
        if ((t & 31) == 0) s_red[c][t >> 5] = v;
    }
    __syncthreads();
    if (t < CLASSES) {
        float s = 0.f;
        #pragma unroll
        for (int w = 0; w < 8; w++) s += s_red[t][w];
        s_logit[t] = s + b_lin[t];
    }
    __syncthreads();
    if (t == 0) {
        float mx = s_logit[0];
        #pragma unroll
        for (int c = 1; c < CLASSES; c++) mx = fmaxf(mx, s_logit[c]);
        float e[CLASSES];
        float sum = 0.f;
        #pragma unroll
        for (int c = 0; c < CLASSES; c++) { e[c] = expf(s_logit[c] - mx); sum += e[c]; }
        float inv = 1.f / sum;
        #pragma unroll
        for (int c = 0; c < CLASSES; c++) out[b * CLASSES + c] = e[c] * inv;
    }
}

// ---------------------------------------------------------------------------
// Launch
// Inputs (metadata order): x, W_ih, W_hh, b_ih, b_hh, W_lin, b_lin
// W_hh is unused: seq_len=1 and h0=0 => rnn_out = tanh(x@W_ih^T + b_ih + b_hh)
// ---------------------------------------------------------------------------
extern "C" void kernel_launch(void* const* d_in, const int* in_sizes, int n_in,
                              void* d_out, int out_size)
{
    const float* x     = (const float*)d_in[0];
    const float* W_ih  = (const float*)d_in[1];
    const float* b_ih  = (const float*)d_in[3];
    const float* b_hh  = (const float*)d_in[4];
    const float* W_lin = (const float*)d_in[5];
    const float* b_lin = (const float*)d_in[6];
    float* out = (float*)d_out;

    dim3 g1(HIDDEN / BN, BATCH / BM);     // (16, 64)
    gemm_tanh_kernel<<<g1, 256>>>(x, W_ih, b_ih, b_hh);
    pool_kernel<<<BATCH, 128>>>();
    scan_kernel<<<NUM_EH, 1024>>>();
    final_kernel<<<BATCH, 256>>>(W_lin, b_lin, out);
}

// round 10
// speedup vs baseline: 1.9955x; 1.9955x over previous
#include <cuda_runtime.h>
#include <cuda_bf16.h>
#include <cstdint>

// Problem constants
#define BATCH   8192
#define INPUT   2048
#define HIDDEN  2048
#define CLASSES 10
#define KPOOL   45
#define NUM_EH  45
#define EST_DIM 270
#define LIN_IN  (HIDDEN + EST_DIM)   // 2318

// -------------------- scratch (device globals, no allocs) -------------------
// NOTE: these symbols are ONLY referenced from device code. Passing them as
// host-side kernel arguments passes the host shadow address; on GB300 (ATS)
// device writes to that host address silently succeed -> R5/R7/R9 bug.
__device__ float g_H[(size_t)BATCH * HIDDEN];
__device__ __nv_bfloat16 g_x_hi[(size_t)BATCH * INPUT];
__device__ __nv_bfloat16 g_x_lo[(size_t)BATCH * INPUT];
__device__ __nv_bfloat16 g_w_hi[(size_t)HIDDEN * INPUT];
__device__ __nv_bfloat16 g_w_lo[(size_t)HIDDEN * INPUT];
__device__ float g_pooledT[NUM_EH * BATCH];
__device__ float g_cs [NUM_EH * BATCH];
__device__ float g_cs2[NUM_EH * BATCH];

__device__ __forceinline__ uint32_t smem_u32(const void* p) {
    uint32_t a;
    asm("{ .reg .u64 t; cvta.to.shared.u64 t, %1; cvt.u32.u64 %0, t; }" : "=r"(a) : "l"(p));
    return a;
}

// ---------------- K0a/K0b: fp32 -> (hi, lo) bf16 split (globals direct) -----
__device__ __forceinline__ void split_store(
    __nv_bfloat16* __restrict__ hi, __nv_bfloat16* __restrict__ lo,
    const float* __restrict__ src, int i)
{
    float4 v = ((const float4*)src)[i];
    __nv_bfloat162 h01 = __floats2bfloat162_rn(v.x, v.y);
    __nv_bfloat162 h23 = __floats2bfloat162_rn(v.z, v.w);
    __nv_bfloat162 l01 = __floats2bfloat162_rn(v.x - __bfloat162float(h01.x),
                                               v.y - __bfloat162float(h01.y));
    __nv_bfloat162 l23 = __floats2bfloat162_rn(v.z - __bfloat162float(h23.x),
                                               v.w - __bfloat162float(h23.y));
    ((__nv_bfloat162*)hi)[i * 2 + 0] = h01;
    ((__nv_bfloat162*)hi)[i * 2 + 1] = h23;
    ((__nv_bfloat162*)lo)[i * 2 + 0] = l01;
    ((__nv_bfloat162*)lo)[i * 2 + 1] = l23;
}

__global__ __launch_bounds__(256) void convert_x(const float* __restrict__ x)
{
    int i = blockIdx.x * blockDim.x + threadIdx.x;
    if (i < BATCH * INPUT / 4) split_store(g_x_hi, g_x_lo, x, i);
}

__global__ __launch_bounds__(256) void convert_w(const float* __restrict__ w)
{
    int i = blockIdx.x * blockDim.x + threadIdx.x;
    if (i < HIDDEN * INPUT / 4) split_store(g_w_hi, g_w_lo, w, i);
}

// -------------------- K1: mma.sync bf16 GEMM + bias + tanh ------------------
// BM=128 x BN=128 x BK=32, 2-stage cp.async, 8 warps (4x2), warp 32x64.
// Dynamic smem = 41984 B < 48KB default.
#define BM 128
#define BN 128
#define KCHUNKS 192                 // 3 terms * 2048 / 32
#define ROW_B   80                  // 32 bf16 = 64B + 16B pad
#define TILE_B  (128 * ROW_B)       // 10240
#define STAGE_BYTES (2 * TILE_B)    // 20480
#define SMEM_TOTAL (1024 + 2 * STAGE_BYTES)   // 41984

__device__ __forceinline__ void mma_bf16(float* c, const uint32_t* a, const uint32_t* b) {
    asm volatile(
        "mma.sync.aligned.m16n8k16.row.col.f32.bf16.bf16.f32 "
        "{%0,%1,%2,%3}, {%4,%5,%6,%7}, {%8,%9}, {%0,%1,%2,%3};"
        : "+f"(c[0]), "+f"(c[1]), "+f"(c[2]), "+f"(c[3])
        : "r"(a[0]), "r"(a[1]), "r"(a[2]), "r"(a[3]), "r"(b[0]), "r"(b[1]));
}

__global__ __launch_bounds__(256, 2) void gemm_mma_kernel(
    const float* __restrict__ b_ih, const float* __restrict__ b_hh)
{
    extern __shared__ char smem[];
    float* s_bias = (float*)smem;
    const uint32_t s_tiles = smem_u32(smem) + 1024;

    const int tid = threadIdx.x;
    const int wid = tid >> 5;
    const int lane = tid & 31;
    const int bm = blockIdx.y * BM;
    const int bn = blockIdx.x * BN;
    const int warp_m = wid >> 1;
    const int warp_n = wid & 1;

    if (tid < BN) s_bias[tid] = b_ih[bn + tid] + b_hh[bn + tid];

    float c[2][8][4];
    #pragma unroll
    for (int i = 0; i < 2; i++)
        #pragma unroll
        for (int j = 0; j < 8; j++)
            #pragma unroll
            for (int q = 0; q < 4; q++) c[i][j][q] = 0.f;

    auto load_stage = [&](int chunk, int stage) {
        int term = chunk >> 6;               // 0:hi*hi  1:hi*lo  2:lo*hi
        int k0 = (chunk & 63) << 5;
        const __nv_bfloat16* A = (term < 2) ? g_x_hi : g_x_lo;
        const __nv_bfloat16* Bp = (term == 1) ? g_w_lo : g_w_hi;
        uint32_t sbase = s_tiles + stage * STAGE_BYTES;
        #pragma unroll
        for (int i = 0; i < 4; i++) {
            int g = tid + (i << 8);
            int isB = (i >= 2);
            int gg = g - (isB ? 512 : 0);
            int row = gg >> 2, c16 = gg & 3;
            const __nv_bfloat16* src =
                (isB ? Bp + (size_t)(bn + row) * INPUT
                     : A + (size_t)(bm + row) * INPUT) + k0 + c16 * 8;
            uint32_t dst = sbase + (isB ? TILE_B : 0) + row * ROW_B + (c16 << 4);
            asm volatile("cp.async.cg.shared.global [%0], [%1], 16;"
                         :: "r"(dst), "l"(src));
        }
        asm volatile("cp.async.commit_group;" ::: "memory");
    };

    load_stage(0, 0);
    load_stage(1, 1);

    const int lr = lane >> 2;
    const int lk = (lane & 3) * 2;

    for (int kt = 0; kt < KCHUNKS; kt++) {
        int s = kt & 1;
        asm volatile("cp.async.wait_group 1;" ::: "memory");
        __syncthreads();

        uint32_t aBase = s_tiles + s * STAGE_BYTES;
        uint32_t bBase = aBase + TILE_B;

        #pragma unroll
        for (int k16 = 0; k16 < 2; k16++) {
            int koff = k16 * 16 + lk;
            uint32_t a[2][4];
            #pragma unroll
            for (int i = 0; i < 2; i++) {
                int m0 = warp_m * 32 + i * 16 + lr;
                uint32_t r00 = aBase + m0 * ROW_B + koff * 2;
                uint32_t r10 = r00 + 8 * ROW_B;
                asm volatile("ld.shared.b32 %0, [%1];" : "=r"(a[i][0]) : "r"(r00));
                asm volatile("ld.shared.b32 %0, [%1];" : "=r"(a[i][1]) : "r"(r10));
                asm volatile("ld.shared.b32 %0, [%1];" : "=r"(a[i][2]) : "r"(r00 + 16));
                asm volatile("ld.shared.b32 %0, [%1];" : "=r"(a[i][3]) : "r"(r10 + 16));
            }
            uint32_t b[8][2];
            #pragma unroll
            for (int j = 0; j < 8; j++) {
                int n0 = warp_n * 64 + j * 8 + lr;
                uint32_t rb = bBase + n0 * ROW_B + koff * 2;
                asm volatile("ld.shared.b32 %0, [%1];" : "=r"(b[j][0]) : "r"(rb));
                asm volatile("ld.shared.b32 %0, [%1];" : "=r"(b[j][1]) : "r"(rb + 16));
            }
            #pragma unroll
            for (int i = 0; i < 2; i++)
                #pragma unroll
                for (int j = 0; j < 8; j++)
                    mma_bf16(c[i][j], a[i], b[j]);
        }

        __syncthreads();
        if (kt + 2 < KCHUNKS)
            load_stage(kt + 2, s);
        else
            asm volatile("cp.async.commit_group;" ::: "memory");
    }

    #pragma unroll
    for (int i = 0; i < 2; i++) {
        int r0 = bm + warp_m * 32 + i * 16 + lr;
        #pragma unroll
        for (int j = 0; j < 8; j++) {
            int ncol = warp_n * 64 + j * 8 + (lane & 3) * 2;
            float bia0 = s_bias[ncol], bia1 = s_bias[ncol + 1];
            float2 o0, o1;
            o0.x = tanhf(c[i][j][0] + bia0);
            o0.y = tanhf(c[i][j][1] + bia1);
            o1.x = tanhf(c[i][j][2] + bia0);
            o1.y = tanhf(c[i][j][3] + bia1);
            *(float2*)(g_H + (size_t)r0 * HIDDEN + bn + ncol) = o0;
            *(float2*)(g_H + (size_t)(r0 + 8) * HIDDEN + bn + ncol) = o1;
        }
    }
}

// -------------------- K2: avg-pool (45 windows of 45), transposed -----------
__global__ __launch_bounds__(128) void pool_kernel()
{
    int b = blockIdx.x;
    __shared__ float sh[NUM_EH * KPOOL];
    const float* row = g_H + (size_t)b * HIDDEN;
    for (int i = threadIdx.x; i < NUM_EH * KPOOL; i += blockDim.x) sh[i] = row[i];
    __syncthreads();
    if (threadIdx.x < NUM_EH) {
        float s = 0.f;
        #pragma unroll
        for (int k = 0; k < KPOOL; k++) s += sh[threadIdx.x * KPOOL + k];
        g_pooledT[threadIdx.x * BATCH + b] = s * (1.0f / KPOOL);
    }
}

// -------------------- K3: per-feature prefix sums over batch ----------------
__global__ __launch_bounds__(1024) void scan_kernel()
{
    int f = blockIdx.x;
    const float* p = g_pooledT + f * BATCH;
    float* cs  = g_cs  + f * BATCH;
    float* cs2 = g_cs2 + f * BATCH;
    int t = threadIdx.x;
    int base = t * 8;

    float v1[8], v2[8];
    float s1 = 0.f, s2 = 0.f;
    #pragma unroll
    for (int i = 0; i < 8; i++) {
        float xv = p[base + i];
        s1 += xv;       v1[i] = s1;
        s2 += xv * xv;  v2[i] = s2;
    }
    __shared__ float sh1[1024], sh2[1024];
    sh1[t] = s1; sh2[t] = s2;
    __syncthreads();
    for (int off = 1; off < 1024; off <<= 1) {
        float a1 = (t >= off) ? sh1[t - off] : 0.f;
        float a2 = (t >= off) ? sh2[t - off] : 0.f;
        __syncthreads();
        sh1[t] += a1; sh2[t] += a2;
        __syncthreads();
    }
    float ex1 = (t > 0) ? sh1[t - 1] : 0.f;
    float ex2 = (t > 0) ? sh2[t - 1] : 0.f;
    #pragma unroll
    for (int i = 0; i < 8; i++) {
        cs [base + i] = v1[i] + ex1;
        cs2[base + i] = v2[i] + ex2;
    }
}

// -------------------- K4: est build + linear + softmax ----------------------
__global__ __launch_bounds__(256) void final_kernel(
    const float* __restrict__ W_lin, const float* __restrict__ b_lin,
    float* __restrict__ out)
{
    int b = blockIdx.x;
    int t = threadIdx.x;
    __shared__ float s_est[EST_DIM];
    __shared__ float s_red[CLASSES][8];
    __shared__ float s_logit[CLASSES];

    for (int e = t; e < EST_DIM; e += 256) {
        int f = e / 6;
        int r = e % 6;
        int j = r >> 1;
        int isvar = r & 1;
        int L = (j == 0) ? 32 : (j == 1) ? 128 : 512;
        float cnt = fminf((float)(b + 1), (float)L);
        float c1 = g_cs [f * BATCH + b];
        float c2 = g_cs2[f * BATCH + b];
        float p1 = (b >= L) ? g_cs [f * BATCH + b - L] : 0.f;
        float p2 = (b >= L) ? g_cs2[f * BATCH + b - L] : 0.f;
        float m = (c1 - p1) / cnt;
        float var = (c2 - p2) / cnt - m * m;
        s_est[e] = isvar ? var : m;
    }
    __syncthreads();

    float acc[CLASSES];
    #pragma unroll
    for (int c = 0; c < CLASSES; c++) acc[c] = 0.f;

    const float* hrow = g_H + (size_t)b * HIDDEN;
    for (int h = t; h < HIDDEN; h += 256) {
        float v = hrow[h];
        #pragma unroll
        for (int c = 0; c < CLASSES; c++)
            acc[c] = fmaf(v, W_lin[c * LIN_IN + h], acc[c]);
    }
    for (int e = t; e < EST_DIM; e += 256) {
        float v = s_est[e];
        #pragma unroll
        for (int c = 0; c < CLASSES; c++)
            acc[c] = fmaf(v, W_lin[c * LIN_IN + HIDDEN + e], acc[c]);
    }
    #pragma unroll
    for (int c = 0; c < CLASSES; c++) {
        float v = acc[c];
        #pragma unroll
        for (int off = 16; off; off >>= 1)
            v += __shfl_down_sync(0xffffffffu, v, off);
        if ((t & 31) == 0) s_red[c][t >> 5] = v;
    }
    __syncthreads();
    if (t < CLASSES) {
        float s = 0.f;
        #pragma unroll
        for (int w = 0; w < 8; w++) s += s_red[t][w];
        s_logit[t] = s + b_lin[t];
    }
    __syncthreads();
    if (t == 0) {
        float mx = s_logit[0];
        #pragma unroll
        for (int c = 1; c < CLASSES; c++) mx = fmaxf(mx, s_logit[c]);
        float e[CLASSES];
        float sum = 0.f;
        #pragma unroll
        for (int c = 0; c < CLASSES; c++) { e[c] = expf(s_logit[c] - mx); sum += e[c]; }
        float inv = 1.f / sum;
        #pragma unroll
        for (int c = 0; c < CLASSES; c++) out[b * CLASSES + c] = e[c] * inv;
    }
}

// ---------------------------------------------------------------------------
// Launch. Inputs: x, W_ih, W_hh(unused), b_ih, b_hh, W_lin, b_lin
// ---------------------------------------------------------------------------
extern "C" void kernel_launch(void* const* d_in, const int* in_sizes, int n_in,
                              void* d_out, int out_size)
{
    const float* x     = (const float*)d_in[0];
    const float* W_ih  = (const float*)d_in[1];
    const float* b_ih  = (const float*)d_in[3];
    const float* b_hh  = (const float*)d_in[4];
    const float* W_lin = (const float*)d_in[5];
    const float* b_lin = (const float*)d_in[6];
    float* out = (float*)d_out;

    convert_x<<<(BATCH * INPUT / 4 + 255) / 256, 256>>>(x);
    convert_w<<<(HIDDEN * INPUT / 4 + 255) / 256, 256>>>(W_ih);
    gemm_mma_kernel<<<dim3(HIDDEN / BN, BATCH / BM), 256, SMEM_TOTAL>>>(b_ih, b_hh);
    pool_kernel<<<BATCH, 128>>>();
    scan_kernel<<<NUM_EH, 1024>>>();
    final_kernel<<<BATCH, 256>>>(W_lin, b_lin, out);
}

// round 11
// speedup vs baseline: 2.0753x; 1.0400x over previous
#include <cuda_runtime.h>
#include <cuda_bf16.h>
#include <cstdint>

// Problem constants
#define BATCH   8192
#define INPUT   2048
#define HIDDEN  2048
#define CLASSES 10
#define KPOOL   45
#define NUM_EH  45
#define EST_DIM 270
#define LIN_IN  (HIDDEN + EST_DIM)   // 2318

// -------------------- scratch (device globals, no allocs) -------------------
// Only referenced from device code (GB300 ATS pitfall: passing these as host
// kernel args passes the host shadow address and device writes silently land
// in host memory).
__device__ float g_H[(size_t)BATCH * HIDDEN];
__device__ __nv_bfloat16 g_x_hi[(size_t)BATCH * INPUT];
__device__ __nv_bfloat16 g_x_lo[(size_t)BATCH * INPUT];
__device__ __nv_bfloat16 g_w_hi[(size_t)HIDDEN * INPUT];
__device__ __nv_bfloat16 g_w_lo[(size_t)HIDDEN * INPUT];
__device__ float g_pooledT[NUM_EH * BATCH];
__device__ float g_cs [NUM_EH * BATCH];
__device__ float g_cs2[NUM_EH * BATCH];

__device__ __forceinline__ uint32_t smem_u32(const void* p) {
    uint32_t a;
    asm("{ .reg .u64 t; cvta.to.shared.u64 t, %1; cvt.u32.u64 %0, t; }" : "=r"(a) : "l"(p));
    return a;
}

// ---------------- K0a/K0b: fp32 -> (hi, lo) bf16 split ----------------------
__device__ __forceinline__ void split_store(
    __nv_bfloat16* __restrict__ hi, __nv_bfloat16* __restrict__ lo,
    const float* __restrict__ src, int i)
{
    float4 v = ((const float4*)src)[i];
    __nv_bfloat162 h01 = __floats2bfloat162_rn(v.x, v.y);
    __nv_bfloat162 h23 = __floats2bfloat162_rn(v.z, v.w);
    __nv_bfloat162 l01 = __floats2bfloat162_rn(v.x - __bfloat162float(h01.x),
                                               v.y - __bfloat162float(h01.y));
    __nv_bfloat162 l23 = __floats2bfloat162_rn(v.z - __bfloat162float(h23.x),
                                               v.w - __bfloat162float(h23.y));
    ((__nv_bfloat162*)hi)[i * 2 + 0] = h01;
    ((__nv_bfloat162*)hi)[i * 2 + 1] = h23;
    ((__nv_bfloat162*)lo)[i * 2 + 0] = l01;
    ((__nv_bfloat162*)lo)[i * 2 + 1] = l23;
}

__global__ __launch_bounds__(256) void convert_x(const float* __restrict__ x)
{
    int i = blockIdx.x * blockDim.x + threadIdx.x;
    if (i < BATCH * INPUT / 4) split_store(g_x_hi, g_x_lo, x, i);
}

__global__ __launch_bounds__(256) void convert_w(const float* __restrict__ w)
{
    int i = blockIdx.x * blockDim.x + threadIdx.x;
    if (i < HIDDEN * INPUT / 4) split_store(g_w_hi, g_w_lo, w, i);
}

// -------------------- K1: mma.sync bf16 GEMM + bias + tanh ------------------
// BM=128 x BN=128 x BK=32, 3-stage cp.async multistage (one sync per chunk),
// 8 warps (4x2), warp 32x64. Fragment logic identical to the R10 passing ver.
#define BM 128
#define BN 128
#define KCHUNKS 192                 // 3 terms * 2048 / 32
#define ROW_B   80                  // 32 bf16 = 64B + 16B pad
#define TILE_B  (128 * ROW_B)       // 10240
#define STAGE_BYTES (2 * TILE_B)    // 20480
#define NSTAGE  3
#define SMEM_TOTAL (1024 + NSTAGE * STAGE_BYTES)   // 62464

__device__ __forceinline__ void mma_bf16(float* c, const uint32_t* a, const uint32_t* b) {
    asm volatile(
        "mma.sync.aligned.m16n8k16.row.col.f32.bf16.bf16.f32 "
        "{%0,%1,%2,%3}, {%4,%5,%6,%7}, {%8,%9}, {%0,%1,%2,%3};"
        : "+f"(c[0]), "+f"(c[1]), "+f"(c[2]), "+f"(c[3])
        : "r"(a[0]), "r"(a[1]), "r"(a[2]), "r"(a[3]), "r"(b[0]), "r"(b[1]));
}

__global__ __launch_bounds__(256, 2) void gemm_mma_kernel(
    const float* __restrict__ b_ih, const float* __restrict__ b_hh)
{
    extern __shared__ char smem[];
    float* s_bias = (float*)smem;
    const uint32_t s_tiles = smem_u32(smem) + 1024;

    const int tid = threadIdx.x;
    const int wid = tid >> 5;
    const int lane = tid & 31;
    const int bm = blockIdx.y * BM;
    const int bn = blockIdx.x * BN;
    const int warp_m = wid >> 1;
    const int warp_n = wid & 1;

    if (tid < BN) s_bias[tid] = b_ih[bn + tid] + b_hh[bn + tid];

    float c[2][8][4];
    #pragma unroll
    for (int i = 0; i < 2; i++)
        #pragma unroll
        for (int j = 0; j < 8; j++)
            #pragma unroll
            for (int q = 0; q < 4; q++) c[i][j][q] = 0.f;

    auto load_stage = [&](int chunk, int stage) {
        int term = chunk >> 6;               // 0:hi*hi  1:hi*lo  2:lo*hi
        int k0 = (chunk & 63) << 5;
        const __nv_bfloat16* A = (term < 2) ? g_x_hi : g_x_lo;
        const __nv_bfloat16* Bp = (term == 1) ? g_w_lo : g_w_hi;
        uint32_t sbase = s_tiles + stage * STAGE_BYTES;
        #pragma unroll
        for (int i = 0; i < 4; i++) {
            int g = tid + (i << 8);
            int isB = (i >= 2);
            int gg = g - (isB ? 512 : 0);
            int row = gg >> 2, c16 = gg & 3;
            const __nv_bfloat16* src =
                (isB ? Bp + (size_t)(bn + row) * INPUT
                     : A + (size_t)(bm + row) * INPUT) + k0 + c16 * 8;
            uint32_t dst = sbase + (isB ? TILE_B : 0) + row * ROW_B + (c16 << 4);
            asm volatile("cp.async.cg.shared.global [%0], [%1], 16;"
                         :: "r"(dst), "l"(src));
        }
        asm volatile("cp.async.commit_group;" ::: "memory");
    };

    load_stage(0, 0);
    load_stage(1, 1);

    const int lr = lane >> 2;
    const int lk = (lane & 3) * 2;

    for (int kt = 0; kt < KCHUNKS; kt++) {
        int s = kt % NSTAGE;
        // Guarantee chunk kt's load is complete. Tail iterations must drain
        // fully (wait_group 1 would let the final real group stay pending).
        if (kt + 2 < KCHUNKS)
            asm volatile("cp.async.wait_group 1;" ::: "memory");
        else
            asm volatile("cp.async.wait_group 0;" ::: "memory");
        __syncthreads();
        // Stage (kt+2)%3 was consumed in iteration kt-1; the sync above makes
        // it safe to overwrite now — prefetch 2 chunks ahead.
        if (kt + 2 < KCHUNKS) load_stage(kt + 2, (kt + 2) % NSTAGE);

        uint32_t aBase = s_tiles + s * STAGE_BYTES;
        uint32_t bBase = aBase + TILE_B;

        #pragma unroll
        for (int k16 = 0; k16 < 2; k16++) {
            int koff = k16 * 16 + lk;
            uint32_t a[2][4];
            #pragma unroll
            for (int i = 0; i < 2; i++) {
                int m0 = warp_m * 32 + i * 16 + lr;
                uint32_t r00 = aBase + m0 * ROW_B + koff * 2;
                uint32_t r10 = r00 + 8 * ROW_B;
                asm volatile("ld.shared.b32 %0, [%1];" : "=r"(a[i][0]) : "r"(r00));
                asm volatile("ld.shared.b32 %0, [%1];" : "=r"(a[i][1]) : "r"(r10));
                asm volatile("ld.shared.b32 %0, [%1];" : "=r"(a[i][2]) : "r"(r00 + 16));
                asm volatile("ld.shared.b32 %0, [%1];" : "=r"(a[i][3]) : "r"(r10 + 16));
            }
            uint32_t b[8][2];
            #pragma unroll
            for (int j = 0; j < 8; j++) {
                int n0 = warp_n * 64 + j * 8 + lr;
                uint32_t rb = bBase + n0 * ROW_B + koff * 2;
                asm volatile("ld.shared.b32 %0, [%1];" : "=r"(b[j][0]) : "r"(rb));
                asm volatile("ld.shared.b32 %0, [%1];" : "=r"(b[j][1]) : "r"(rb + 16));
            }
            #pragma unroll
            for (int i = 0; i < 2; i++)
                #pragma unroll
                for (int j = 0; j < 8; j++)
                    mma_bf16(c[i][j], a[i], b[j]);
        }
    }

    #pragma unroll
    for (int i = 0; i < 2; i++) {
        int r0 = bm + warp_m * 32 + i * 16 + lr;
        #pragma unroll
        for (int j = 0; j < 8; j++) {
            int ncol = warp_n * 64 + j * 8 + (lane & 3) * 2;
            float bia0 = s_bias[ncol], bia1 = s_bias[ncol + 1];
            float2 o0, o1;
            o0.x = tanhf(c[i][j][0] + bia0);
            o0.y = tanhf(c[i][j][1] + bia1);
            o1.x = tanhf(c[i][j][2] + bia0);
            o1.y = tanhf(c[i][j][3] + bia1);
            *(float2*)(g_H + (size_t)r0 * HIDDEN + bn + ncol) = o0;
            *(float2*)(g_H + (size_t)(r0 + 8) * HIDDEN + bn + ncol) = o1;
        }
    }
}

// -------------------- K2: avg-pool (45 windows of 45), transposed -----------
__global__ __launch_bounds__(128) void pool_kernel()
{
    int b = blockIdx.x;
    __shared__ float sh[NUM_EH * KPOOL];
    const float* row = g_H + (size_t)b * HIDDEN;
    for (int i = threadIdx.x; i < NUM_EH * KPOOL; i += blockDim.x) sh[i] = row[i];
    __syncthreads();
    if (threadIdx.x < NUM_EH) {
        float s = 0.f;
        #pragma unroll
        for (int k = 0; k < KPOOL; k++) s += sh[threadIdx.x * KPOOL + k];
        g_pooledT[threadIdx.x * BATCH + b] = s * (1.0f / KPOOL);
    }
}

// -------------------- K3: per-feature prefix sums over batch ----------------
__global__ __launch_bounds__(1024) void scan_kernel()
{
    int f = blockIdx.x;
    const float* p = g_pooledT + f * BATCH;
    float* cs  = g_cs  + f * BATCH;
    float* cs2 = g_cs2 + f * BATCH;
    int t = threadIdx.x;
    int base = t * 8;

    float v1[8], v2[8];
    float s1 = 0.f, s2 = 0.f;
    #pragma unroll
    for (int i = 0; i < 8; i++) {
        float xv = p[base + i];
        s1 += xv;       v1[i] = s1;
        s2 += xv * xv;  v2[i] = s2;
    }
    __shared__ float sh1[1024], sh2[1024];
    sh1[t] = s1; sh2[t] = s2;
    __syncthreads();
    for (int off = 1; off < 1024; off <<= 1) {
        float a1 = (t >= off) ? sh1[t - off] : 0.f;
        float a2 = (t >= off) ? sh2[t - off] : 0.f;
        __syncthreads();
        sh1[t] += a1; sh2[t] += a2;
        __syncthreads();
    }
    float ex1 = (t > 0) ? sh1[t - 1] : 0.f;
    float ex2 = (t > 0) ? sh2[t - 1] : 0.f;
    #pragma unroll
    for (int i = 0; i < 8; i++) {
        cs [base + i] = v1[i] + ex1;
        cs2[base + i] = v2[i] + ex2;
    }
}

// -------------------- K4: est + linear + softmax, 32 samples/block ----------
// W_lin hidden part staged through smem (4 chunks of 512): eliminates the
// per-sample 92KB W_lin re-read (was ~760MB of L2 traffic).
#define FB 32                      // samples per block
#define HCHUNK 512

__global__ __launch_bounds__(256) void final_kernel(
    const float* __restrict__ W_lin, const float* __restrict__ b_lin,
    float* __restrict__ out)
{
    __shared__ float sW[CLASSES][HCHUNK];   // 20 KB
    const int t = threadIdx.x;
    const int wid = t >> 5;
    const int lane = t & 31;
    const int b0 = blockIdx.x * FB + wid * 4;   // this warp's 4 samples

    float acc[4][CLASSES];
    #pragma unroll
    for (int si = 0; si < 4; si++)
        #pragma unroll
        for (int c = 0; c < CLASSES; c++) acc[si][c] = 0.f;

    // ---- hidden part: 4 chunks of 512 via smem-tiled W_lin ----------------
    for (int ch = 0; ch < HIDDEN / HCHUNK; ch++) {
        int h0 = ch * HCHUNK;
        __syncthreads();
        for (int i = t; i < CLASSES * HCHUNK; i += 256) {
            int c = i / HCHUNK, h = i % HCHUNK;
            sW[c][h] = W_lin[c * LIN_IN + h0 + h];
        }
        __syncthreads();
        #pragma unroll 4
        for (int k = 0; k < HCHUNK / 32; k++) {
            int h = k * 32 + lane;
            float v[4];
            #pragma unroll
            for (int si = 0; si < 4; si++)
                v[si] = g_H[(size_t)(b0 + si) * HIDDEN + h0 + h];
            #pragma unroll
            for (int c = 0; c < CLASSES; c++) {
                float w = sW[c][h];
                #pragma unroll
                for (int si = 0; si < 4; si++)
                    acc[si][c] = fmaf(v[si], w, acc[si][c]);
            }
        }
    }

    // ---- est part: compute on the fly from cs/cs2 -------------------------
    for (int e = lane; e < EST_DIM; e += 32) {
        int f = e / 6;
        int r = e % 6;
        int j = r >> 1;
        int isvar = r & 1;
        int L = (j == 0) ? 32 : (j == 1) ? 128 : 512;
        float wv[CLASSES];
        #pragma unroll
        for (int c = 0; c < CLASSES; c++)
            wv[c] = W_lin[c * LIN_IN + HIDDEN + e];
        #pragma unroll
        for (int si = 0; si < 4; si++) {
            int b = b0 + si;
            float cnt = fminf((float)(b + 1), (float)L);
            float c1 = g_cs [f * BATCH + b];
            float c2 = g_cs2[f * BATCH + b];
            float p1 = (b >= L) ? g_cs [f * BATCH + b - L] : 0.f;
            float p2 = (b >= L) ? g_cs2[f * BATCH + b - L] : 0.f;
            float m = (c1 - p1) / cnt;
            float var = (c2 - p2) / cnt - m * m;
            float v = isvar ? var : m;
            #pragma unroll
            for (int c = 0; c < CLASSES; c++)
                acc[si][c] = fmaf(v, wv[c], acc[si][c]);
        }
    }

    // ---- warp reduce + softmax --------------------------------------------
    #pragma unroll
    for (int si = 0; si < 4; si++)
        #pragma unroll
        for (int c = 0; c < CLASSES; c++) {
            float v = acc[si][c];
            #pragma unroll
            for (int off = 16; off; off >>= 1)
                v += __shfl_down_sync(0xffffffffu, v, off);
            acc[si][c] = v;
        }
    if (lane == 0) {
        #pragma unroll
        for (int si = 0; si < 4; si++) {
            float lg[CLASSES];
            float mx = -1e30f;
            #pragma unroll
            for (int c = 0; c < CLASSES; c++) {
                lg[c] = acc[si][c] + b_lin[c];
                mx = fmaxf(mx, lg[c]);
            }
            float sum = 0.f;
            #pragma unroll
            for (int c = 0; c < CLASSES; c++) { lg[c] = expf(lg[c] - mx); sum += lg[c]; }
            float inv = 1.f / sum;
            #pragma unroll
            for (int c = 0; c < CLASSES; c++)
                out[(b0 + si) * CLASSES + c] = lg[c] * inv;
        }
    }
}

// ---------------------------------------------------------------------------
// Launch. Inputs: x, W_ih, W_hh(unused), b_ih, b_hh, W_lin, b_lin
// ---------------------------------------------------------------------------
extern "C" void kernel_launch(void* const* d_in, const int* in_sizes, int n_in,
                              void* d_out, int out_size)
{
    const float* x     = (const float*)d_in[0];
    const float* W_ih  = (const float*)d_in[1];
    const float* b_ih  = (const float*)d_in[3];
    const float* b_hh  = (const float*)d_in[4];
    const float* W_lin = (const float*)d_in[5];
    const float* b_lin = (const float*)d_in[6];
    float* out = (float*)d_out;

    cudaFuncSetAttribute(gemm_mma_kernel,
                         cudaFuncAttributeMaxDynamicSharedMemorySize, SMEM_TOTAL);

    convert_x<<<(BATCH * INPUT / 4 + 255) / 256, 256>>>(x);
    convert_w<<<(HIDDEN * INPUT / 4 + 255) / 256, 256>>>(W_ih);
    gemm_mma_kernel<<<dim3(HIDDEN / BN, BATCH / BM), 256, SMEM_TOTAL>>>(b_ih, b_hh);
    pool_kernel<<<BATCH, 128>>>();
    scan_kernel<<<NUM_EH, 1024>>>();
    final_kernel<<<BATCH / FB, 256>>>(W_lin, b_lin, out);
}

// round 12
// speedup vs baseline: 2.8529x; 1.3747x over previous
#include <cuda_runtime.h>
#include <cuda_bf16.h>
#include <cuda_fp16.h>
#include <cstdint>

// Problem constants
#define BATCH   8192
#define INPUT   2048
#define HIDDEN  2048
#define CLASSES 10
#define KPOOL   45
#define NUM_EH  45
#define EST_DIM 270
#define LIN_IN  (HIDDEN + EST_DIM)   // 2318

// -------------------- scratch (device globals, no allocs) -------------------
// Only referenced from device code (GB300 ATS pitfall: passing these as host
// kernel args passes the host shadow address; device writes silently succeed).
__device__ float g_H[(size_t)BATCH * HIDDEN];
__device__ __half g_x_hi[(size_t)BATCH * INPUT];
__device__ __half g_x_lo[(size_t)BATCH * INPUT];
__device__ __half g_w_h [(size_t)HIDDEN * INPUT];
__device__ float g_pooledT[NUM_EH * BATCH];
__device__ float g_cs [NUM_EH * BATCH];
__device__ float g_cs2[NUM_EH * BATCH];

__device__ __forceinline__ uint32_t smem_u32(const void* p) {
    uint32_t a;
    asm("{ .reg .u64 t; cvta.to.shared.u64 t, %1; cvt.u32.u64 %0, t; }" : "=r"(a) : "l"(p));
    return a;
}

// ---------------- K0a: x fp32 -> (hi, lo) fp16 split ------------------------
__global__ __launch_bounds__(256) void convert_x(const float* __restrict__ x)
{
    int i = blockIdx.x * blockDim.x + threadIdx.x;
    if (i >= BATCH * INPUT / 4) return;
    float4 v = ((const float4*)x)[i];
    __half2 h01 = __float22half2_rn(make_float2(v.x, v.y));
    __half2 h23 = __float22half2_rn(make_float2(v.z, v.w));
    __half2 l01 = __float22half2_rn(make_float2(v.x - __half2float(__low2half(h01)),
                                                v.y - __half2float(__high2half(h01))));
    __half2 l23 = __float22half2_rn(make_float2(v.z - __half2float(__low2half(h23)),
                                                v.w - __half2float(__high2half(h23))));
    ((__half2*)g_x_hi)[i * 2 + 0] = h01;
    ((__half2*)g_x_hi)[i * 2 + 1] = h23;
    ((__half2*)g_x_lo)[i * 2 + 0] = l01;
    ((__half2*)g_x_lo)[i * 2 + 1] = l23;
}

// ---------------- K0b: W fp32 -> single fp16 --------------------------------
__global__ __launch_bounds__(256) void convert_w(const float* __restrict__ w)
{
    int i = blockIdx.x * blockDim.x + threadIdx.x;
    if (i >= HIDDEN * INPUT / 4) return;
    float4 v = ((const float4*)w)[i];
    ((__half2*)g_w_h)[i * 2 + 0] = __float22half2_rn(make_float2(v.x, v.y));
    ((__half2*)g_w_h)[i * 2 + 1] = __float22half2_rn(make_float2(v.z, v.w));
}

// -------------------- K1: mma.sync fp16 GEMM + bias + tanh ------------------
// C = tanh( (x_hi + x_lo) @ W^T + bias ): 2 terms, K_total = 2*2048.
// BM=128 x BN=128 x BK=32, 3-stage cp.async, 8 warps (4x2), warp 32x64.
// Structure identical to the passing R11 kernel; only dtype/terms changed.
#define BM 128
#define BN 128
#define KCHUNKS 128                 // 2 terms * 2048 / 32
#define ROW_B   80                  // 32 fp16 = 64B + 16B pad
#define TILE_B  (128 * ROW_B)       // 10240
#define STAGE_BYTES (2 * TILE_B)    // 20480
#define NSTAGE  3
#define SMEM_TOTAL (1024 + NSTAGE * STAGE_BYTES)   // 62464

__device__ __forceinline__ void mma_f16(float* c, const uint32_t* a, const uint32_t* b) {
    asm volatile(
        "mma.sync.aligned.m16n8k16.row.col.f32.f16.f16.f32 "
        "{%0,%1,%2,%3}, {%4,%5,%6,%7}, {%8,%9}, {%0,%1,%2,%3};"
        : "+f"(c[0]), "+f"(c[1]), "+f"(c[2]), "+f"(c[3])
        : "r"(a[0]), "r"(a[1]), "r"(a[2]), "r"(a[3]), "r"(b[0]), "r"(b[1]));
}

__global__ __launch_bounds__(256, 2) void gemm_mma_kernel(
    const float* __restrict__ b_ih, const float* __restrict__ b_hh)
{
    extern __shared__ char smem[];
    float* s_bias = (float*)smem;
    const uint32_t s_tiles = smem_u32(smem) + 1024;

    const int tid = threadIdx.x;
    const int wid = tid >> 5;
    const int lane = tid & 31;
    const int bm = blockIdx.y * BM;
    const int bn = blockIdx.x * BN;
    const int warp_m = wid >> 1;
    const int warp_n = wid & 1;

    if (tid < BN) s_bias[tid] = b_ih[bn + tid] + b_hh[bn + tid];

    float c[2][8][4];
    #pragma unroll
    for (int i = 0; i < 2; i++)
        #pragma unroll
        for (int j = 0; j < 8; j++)
            #pragma unroll
            for (int q = 0; q < 4; q++) c[i][j][q] = 0.f;

    auto load_stage = [&](int chunk, int stage) {
        int term = chunk >> 6;               // 0: x_hi*W  1: x_lo*W
        int k0 = (chunk & 63) << 5;
        const __half* A = term ? g_x_lo : g_x_hi;
        uint32_t sbase = s_tiles + stage * STAGE_BYTES;
        #pragma unroll
        for (int i = 0; i < 4; i++) {
            int g = tid + (i << 8);
            int isB = (i >= 2);
            int gg = g - (isB ? 512 : 0);
            int row = gg >> 2, c16 = gg & 3;
            const __half* src =
                (isB ? g_w_h + (size_t)(bn + row) * INPUT
                     : A + (size_t)(bm + row) * INPUT) + k0 + c16 * 8;
            uint32_t dst = sbase + (isB ? TILE_B : 0) + row * ROW_B + (c16 << 4);
            asm volatile("cp.async.cg.shared.global [%0], [%1], 16;"
                         :: "r"(dst), "l"(src));
        }
        asm volatile("cp.async.commit_group;" ::: "memory");
    };

    load_stage(0, 0);
    load_stage(1, 1);

    const int lr = lane >> 2;
    const int lk = (lane & 3) * 2;

    for (int kt = 0; kt < KCHUNKS; kt++) {
        int s = kt % NSTAGE;
        if (kt + 2 < KCHUNKS)
            asm volatile("cp.async.wait_group 1;" ::: "memory");
        else
            asm volatile("cp.async.wait_group 0;" ::: "memory");
        __syncthreads();
        if (kt + 2 < KCHUNKS) load_stage(kt + 2, (kt + 2) % NSTAGE);

        uint32_t aBase = s_tiles + s * STAGE_BYTES;
        uint32_t bBase = aBase + TILE_B;

        #pragma unroll
        for (int k16 = 0; k16 < 2; k16++) {
            int koff = k16 * 16 + lk;
            uint32_t a[2][4];
            #pragma unroll
            for (int i = 0; i < 2; i++) {
                int m0 = warp_m * 32 + i * 16 + lr;
                uint32_t r00 = aBase + m0 * ROW_B + koff * 2;
                uint32_t r10 = r00 + 8 * ROW_B;
                asm volatile("ld.shared.b32 %0, [%1];" : "=r"(a[i][0]) : "r"(r00));
                asm volatile("ld.shared.b32 %0, [%1];" : "=r"(a[i][1]) : "r"(r10));
                asm volatile("ld.shared.b32 %0, [%1];" : "=r"(a[i][2]) : "r"(r00 + 16));
                asm volatile("ld.shared.b32 %0, [%1];" : "=r"(a[i][3]) : "r"(r10 + 16));
            }
            uint32_t b[8][2];
            #pragma unroll
            for (int j = 0; j < 8; j++) {
                int n0 = warp_n * 64 + j * 8 + lr;
                uint32_t rb = bBase + n0 * ROW_B + koff * 2;
                asm volatile("ld.shared.b32 %0, [%1];" : "=r"(b[j][0]) : "r"(rb));
                asm volatile("ld.shared.b32 %0, [%1];" : "=r"(b[j][1]) : "r"(rb + 16));
            }
            #pragma unroll
            for (int i = 0; i < 2; i++)
                #pragma unroll
                for (int j = 0; j < 8; j++)
                    mma_f16(c[i][j], a[i], b[j]);
        }
    }

    #pragma unroll
    for (int i = 0; i < 2; i++) {
        int r0 = bm + warp_m * 32 + i * 16 + lr;
        #pragma unroll
        for (int j = 0; j < 8; j++) {
            int ncol = warp_n * 64 + j * 8 + (lane & 3) * 2;
            float bia0 = s_bias[ncol], bia1 = s_bias[ncol + 1];
            float2 o0, o1;
            o0.x = tanhf(c[i][j][0] + bia0);
            o0.y = tanhf(c[i][j][1] + bia1);
            o1.x = tanhf(c[i][j][2] + bia0);
            o1.y = tanhf(c[i][j][3] + bia1);
            *(float2*)(g_H + (size_t)r0 * HIDDEN + bn + ncol) = o0;
            *(float2*)(g_H + (size_t)(r0 + 8) * HIDDEN + bn + ncol) = o1;
        }
    }
}

// -------------------- K2: avg-pool (45 windows of 45), transposed -----------
__global__ __launch_bounds__(128) void pool_kernel()
{
    int b = blockIdx.x;
    __shared__ float sh[NUM_EH * KPOOL];
    const float* row = g_H + (size_t)b * HIDDEN;
    for (int i = threadIdx.x; i < NUM_EH * KPOOL; i += blockDim.x) sh[i] = row[i];
    __syncthreads();
    if (threadIdx.x < NUM_EH) {
        float s = 0.f;
        #pragma unroll
        for (int k = 0; k < KPOOL; k++) s += sh[threadIdx.x * KPOOL + k];
        g_pooledT[threadIdx.x * BATCH + b] = s * (1.0f / KPOOL);
    }
}

// -------------------- K3: per-feature prefix sums over batch ----------------
__global__ __launch_bounds__(1024) void scan_kernel()
{
    int f = blockIdx.x;
    const float* p = g_pooledT + f * BATCH;
    float* cs  = g_cs  + f * BATCH;
    float* cs2 = g_cs2 + f * BATCH;
    int t = threadIdx.x;
    int base = t * 8;

    float v1[8], v2[8];
    float s1 = 0.f, s2 = 0.f;
    #pragma unroll
    for (int i = 0; i < 8; i++) {
        float xv = p[base + i];
        s1 += xv;       v1[i] = s1;
        s2 += xv * xv;  v2[i] = s2;
    }
    __shared__ float sh1[1024], sh2[1024];
    sh1[t] = s1; sh2[t] = s2;
    __syncthreads();
    for (int off = 1; off < 1024; off <<= 1) {
        float a1 = (t >= off) ? sh1[t - off] : 0.f;
        float a2 = (t >= off) ? sh2[t - off] : 0.f;
        __syncthreads();
        sh1[t] += a1; sh2[t] += a2;
        __syncthreads();
    }
    float ex1 = (t > 0) ? sh1[t - 1] : 0.f;
    float ex2 = (t > 0) ? sh2[t - 1] : 0.f;
    #pragma unroll
    for (int i = 0; i < 8; i++) {
        cs [base + i] = v1[i] + ex1;
        cs2[base + i] = v2[i] + ex2;
    }
}

// -------------------- K4: est + linear + softmax, 32 samples/block ----------
#define FB 32
#define HCHUNK 512

__global__ __launch_bounds__(256) void final_kernel(
    const float* __restrict__ W_lin, const float* __restrict__ b_lin,
    float* __restrict__ out)
{
    __shared__ float sW[CLASSES][HCHUNK];   // 20 KB
    const int t = threadIdx.x;
    const int wid = t >> 5;
    const int lane = t & 31;
    const int b0 = blockIdx.x * FB + wid * 4;

    float acc[4][CLASSES];
    #pragma unroll
    for (int si = 0; si < 4; si++)
        #pragma unroll
        for (int c = 0; c < CLASSES; c++) acc[si][c] = 0.f;

    for (int ch = 0; ch < HIDDEN / HCHUNK; ch++) {
        int h0 = ch * HCHUNK;
        __syncthreads();
        for (int i = t; i < CLASSES * HCHUNK; i += 256) {
            int c = i / HCHUNK, h = i % HCHUNK;
            sW[c][h] = W_lin[c * LIN_IN + h0 + h];
        }
        __syncthreads();
        #pragma unroll 4
        for (int k = 0; k < HCHUNK / 32; k++) {
            int h = k * 32 + lane;
            float v[4];
            #pragma unroll
            for (int si = 0; si < 4; si++)
                v[si] = g_H[(size_t)(b0 + si) * HIDDEN + h0 + h];
            #pragma unroll
            for (int c = 0; c < CLASSES; c++) {
                float w = sW[c][h];
                #pragma unroll
                for (int si = 0; si < 4; si++)
                    acc[si][c] = fmaf(v[si], w, acc[si][c]);
            }
        }
    }

    for (int e = lane; e < EST_DIM; e += 32) {
        int f = e / 6;
        int r = e % 6;
        int j = r >> 1;
        int isvar = r & 1;
        int L = (j == 0) ? 32 : (j == 1) ? 128 : 512;
        float wv[CLASSES];
        #pragma unroll
        for (int c = 0; c < CLASSES; c++)
            wv[c] = W_lin[c * LIN_IN + HIDDEN + e];
        #pragma unroll
        for (int si = 0; si < 4; si++) {
            int b = b0 + si;
            float cnt = fminf((float)(b + 1), (float)L);
            float c1 = g_cs [f * BATCH + b];
            float c2 = g_cs2[f * BATCH + b];
            float p1 = (b >= L) ? g_cs [f * BATCH + b - L] : 0.f;
            float p2 = (b >= L) ? g_cs2[f * BATCH + b - L] : 0.f;
            float m = (c1 - p1) / cnt;
            float var = (c2 - p2) / cnt - m * m;
            float v = isvar ? var : m;
            #pragma unroll
            for (int c = 0; c < CLASSES; c++)
                acc[si][c] = fmaf(v, wv[c], acc[si][c]);
        }
    }

    #pragma unroll
    for (int si = 0; si < 4; si++)
        #pragma unroll
        for (int c = 0; c < CLASSES; c++) {
            float v = acc[si][c];
            #pragma unroll
            for (int off = 16; off; off >>= 1)
                v += __shfl_down_sync(0xffffffffu, v, off);
            acc[si][c] = v;
        }
    if (lane == 0) {
        #pragma unroll
        for (int si = 0; si < 4; si++) {
            float lg[CLASSES];
            float mx = -1e30f;
            #pragma unroll
            for (int c = 0; c < CLASSES; c++) {
                lg[c] = acc[si][c] + b_lin[c];
                mx = fmaxf(mx, lg[c]);
            }
            float sum = 0.f;
            #pragma unroll
            for (int c = 0; c < CLASSES; c++) { lg[c] = expf(lg[c] - mx); sum += lg[c]; }
            float inv = 1.f / sum;
            #pragma unroll
            for (int c = 0; c < CLASSES; c++)
                out[(b0 + si) * CLASSES + c] = lg[c] * inv;
        }
    }
}

// ---------------------------------------------------------------------------
// Launch. Inputs: x, W_ih, W_hh(unused), b_ih, b_hh, W_lin, b_lin
// ---------------------------------------------------------------------------
extern "C" void kernel_launch(void* const* d_in, const int* in_sizes, int n_in,
                              void* d_out, int out_size)
{
    const float* x     = (const float*)d_in[0];
    const float* W_ih  = (const float*)d_in[1];
    const float* b_ih  = (const float*)d_in[3];
    const float* b_hh  = (const float*)d_in[4];
    const float* W_lin = (const float*)d_in[5];
    const float* b_lin = (const float*)d_in[6];
    float* out = (float*)d_out;

    cudaFuncSetAttribute(gemm_mma_kernel,
                         cudaFuncAttributeMaxDynamicSharedMemorySize, SMEM_TOTAL);

    convert_x<<<(BATCH * INPUT / 4 + 255) / 256, 256>>>(x);
    convert_w<<<(HIDDEN * INPUT / 4 + 255) / 256, 256>>>(W_ih);
    gemm_mma_kernel<<<dim3(HIDDEN / BN, BATCH / BM), 256, SMEM_TOTAL>>>(b_ih, b_hh);
    pool_kernel<<<BATCH, 128>>>();
    scan_kernel<<<NUM_EH, 1024>>>();
    final_kernel<<<BATCH / FB, 256>>>(W_lin, b_lin, out);
}

// round 13
// speedup vs baseline: 4.9980x; 1.7519x over previous
#include <cuda_runtime.h>
#include <cuda_fp16.h>
#include <cstdint>

// Problem constants
#define BATCH   8192
#define INPUT   2048
#define HIDDEN  2048
#define CLASSES 10
#define KPOOL   45
#define NUM_EH  45
#define EST_DIM 270
#define LIN_IN  (HIDDEN + EST_DIM)   // 2318

// -------------------- scratch (device globals, no allocs) -------------------
// Only referenced from device code (GB300 ATS pitfall: passing these as host
// kernel args passes the host shadow address; device writes silently succeed).
__device__ float g_H[(size_t)BATCH * HIDDEN];
__device__ __half g_x_h[(size_t)BATCH * INPUT];
__device__ __half g_w_h[(size_t)HIDDEN * INPUT];
__device__ float g_pooledT[NUM_EH * BATCH];
__device__ float g_cs [NUM_EH * BATCH];
__device__ float g_cs2[NUM_EH * BATCH];

__device__ __forceinline__ uint32_t smem_u32(const void* p) {
    uint32_t a;
    asm("{ .reg .u64 t; cvta.to.shared.u64 t, %1; cvt.u32.u64 %0, t; }" : "=r"(a) : "l"(p));
    return a;
}

// ---------------- K0a: x fp32 -> fp16 ---------------------------------------
__global__ __launch_bounds__(256) void convert_x(const float* __restrict__ x)
{
    int i = blockIdx.x * blockDim.x + threadIdx.x;
    if (i >= BATCH * INPUT / 4) return;
    float4 v = ((const float4*)x)[i];
    ((__half2*)g_x_h)[i * 2 + 0] = __float22half2_rn(make_float2(v.x, v.y));
    ((__half2*)g_x_h)[i * 2 + 1] = __float22half2_rn(make_float2(v.z, v.w));
}

// ---------------- K0b: W fp32 -> fp16 ---------------------------------------
__global__ __launch_bounds__(256) void convert_w(const float* __restrict__ w)
{
    int i = blockIdx.x * blockDim.x + threadIdx.x;
    if (i >= HIDDEN * INPUT / 4) return;
    float4 v = ((const float4*)w)[i];
    ((__half2*)g_w_h)[i * 2 + 0] = __float22half2_rn(make_float2(v.x, v.y));
    ((__half2*)g_w_h)[i * 2 + 1] = __float22half2_rn(make_float2(v.z, v.w));
}

// -------------------- K1: mma.sync fp16 GEMM + bias + tanh ------------------
// C = tanh( x @ W^T + bias ), single fp16 term, K=2048.
// BM=128 x BN=128 x BK=32, 3-stage cp.async, 8 warps (4x2), warp 32x64.
#define BM 128
#define BN 128
#define KCHUNKS 64                  // 2048 / 32
#define ROW_B   80                  // 32 fp16 = 64B + 16B pad
#define TILE_B  (128 * ROW_B)       // 10240
#define STAGE_BYTES (2 * TILE_B)    // 20480
#define NSTAGE  3
#define SMEM_TOTAL (1024 + NSTAGE * STAGE_BYTES)   // 62464

__device__ __forceinline__ void mma_f16(float* c, const uint32_t* a, const uint32_t* b) {
    asm volatile(
        "mma.sync.aligned.m16n8k16.row.col.f32.f16.f16.f32 "
        "{%0,%1,%2,%3}, {%4,%5,%6,%7}, {%8,%9}, {%0,%1,%2,%3};"
        : "+f"(c[0]), "+f"(c[1]), "+f"(c[2]), "+f"(c[3])
        : "r"(a[0]), "r"(a[1]), "r"(a[2]), "r"(a[3]), "r"(b[0]), "r"(b[1]));
}

__global__ __launch_bounds__(256, 2) void gemm_mma_kernel(
    const float* __restrict__ b_ih, const float* __restrict__ b_hh)
{
    extern __shared__ char smem[];
    float* s_bias = (float*)smem;
    const uint32_t s_tiles = smem_u32(smem) + 1024;

    const int tid = threadIdx.x;
    const int wid = tid >> 5;
    const int lane = tid & 31;
    const int bm = blockIdx.y * BM;
    const int bn = blockIdx.x * BN;
    const int warp_m = wid >> 1;
    const int warp_n = wid & 1;

    if (tid < BN) s_bias[tid] = b_ih[bn + tid] + b_hh[bn + tid];

    float c[2][8][4];
    #pragma unroll
    for (int i = 0; i < 2; i++)
        #pragma unroll
        for (int j = 0; j < 8; j++)
            #pragma unroll
            for (int q = 0; q < 4; q++) c[i][j][q] = 0.f;

    auto load_stage = [&](int chunk, int stage) {
        int k0 = chunk << 5;
        uint32_t sbase = s_tiles + stage * STAGE_BYTES;
        #pragma unroll
        for (int i = 0; i < 4; i++) {
            int g = tid + (i << 8);
            int isB = (i >= 2);
            int gg = g - (isB ? 512 : 0);
            int row = gg >> 2, c16 = gg & 3;
            const __half* src =
                (isB ? g_w_h + (size_t)(bn + row) * INPUT
                     : g_x_h + (size_t)(bm + row) * INPUT) + k0 + c16 * 8;
            uint32_t dst = sbase + (isB ? TILE_B : 0) + row * ROW_B + (c16 << 4);
            asm volatile("cp.async.cg.shared.global [%0], [%1], 16;"
                         :: "r"(dst), "l"(src));
        }
        asm volatile("cp.async.commit_group;" ::: "memory");
    };

    load_stage(0, 0);
    load_stage(1, 1);

    const int lr = lane >> 2;
    const int lk = (lane & 3) * 2;

    for (int kt = 0; kt < KCHUNKS; kt++) {
        int s = kt % NSTAGE;
        if (kt + 2 < KCHUNKS)
            asm volatile("cp.async.wait_group 1;" ::: "memory");
        else
            asm volatile("cp.async.wait_group 0;" ::: "memory");
        __syncthreads();
        if (kt + 2 < KCHUNKS) load_stage(kt + 2, (kt + 2) % NSTAGE);

        uint32_t aBase = s_tiles + s * STAGE_BYTES;
        uint32_t bBase = aBase + TILE_B;

        #pragma unroll
        for (int k16 = 0; k16 < 2; k16++) {
            int koff = k16 * 16 + lk;
            uint32_t a[2][4];
            #pragma unroll
            for (int i = 0; i < 2; i++) {
                int m0 = warp_m * 32 + i * 16 + lr;
                uint32_t r00 = aBase + m0 * ROW_B + koff * 2;
                uint32_t r10 = r00 + 8 * ROW_B;
                asm volatile("ld.shared.b32 %0, [%1];" : "=r"(a[i][0]) : "r"(r00));
                asm volatile("ld.shared.b32 %0, [%1];" : "=r"(a[i][1]) : "r"(r10));
                asm volatile("ld.shared.b32 %0, [%1];" : "=r"(a[i][2]) : "r"(r00 + 16));
                asm volatile("ld.shared.b32 %0, [%1];" : "=r"(a[i][3]) : "r"(r10 + 16));
            }
            uint32_t b[8][2];
            #pragma unroll
            for (int j = 0; j < 8; j++) {
                int n0 = warp_n * 64 + j * 8 + lr;
                uint32_t rb = bBase + n0 * ROW_B + koff * 2;
                asm volatile("ld.shared.b32 %0, [%1];" : "=r"(b[j][0]) : "r"(rb));
                asm volatile("ld.shared.b32 %0, [%1];" : "=r"(b[j][1]) : "r"(rb + 16));
            }
            #pragma unroll
            for (int i = 0; i < 2; i++)
                #pragma unroll
                for (int j = 0; j < 8; j++)
                    mma_f16(c[i][j], a[i], b[j]);
        }
    }

    #pragma unroll
    for (int i = 0; i < 2; i++) {
        int r0 = bm + warp_m * 32 + i * 16 + lr;
        #pragma unroll
        for (int j = 0; j < 8; j++) {
            int ncol = warp_n * 64 + j * 8 + (lane & 3) * 2;
            float bia0 = s_bias[ncol], bia1 = s_bias[ncol + 1];
            float2 o0, o1;
            o0.x = tanhf(c[i][j][0] + bia0);
            o0.y = tanhf(c[i][j][1] + bia1);
            o1.x = tanhf(c[i][j][2] + bia0);
            o1.y = tanhf(c[i][j][3] + bia1);
            *(float2*)(g_H + (size_t)r0 * HIDDEN + bn + ncol) = o0;
            *(float2*)(g_H + (size_t)(r0 + 8) * HIDDEN + bn + ncol) = o1;
        }
    }
}

// -------------------- K2: avg-pool (45 windows of 45), transposed -----------
__global__ __launch_bounds__(128) void pool_kernel()
{
    int b = blockIdx.x;
    __shared__ float sh[NUM_EH * KPOOL];
    const float* row = g_H + (size_t)b * HIDDEN;
    for (int i = threadIdx.x; i < NUM_EH * KPOOL; i += blockDim.x) sh[i] = row[i];
    __syncthreads();
    if (threadIdx.x < NUM_EH) {
        float s = 0.f;
        #pragma unroll
        for (int k = 0; k < KPOOL; k++) s += sh[threadIdx.x * KPOOL + k];
        g_pooledT[threadIdx.x * BATCH + b] = s * (1.0f / KPOOL);
    }
}

// -------------------- K3: per-feature prefix sums over batch ----------------
__global__ __launch_bounds__(1024) void scan_kernel()
{
    int f = blockIdx.x;
    const float* p = g_pooledT + f * BATCH;
    float* cs  = g_cs  + f * BATCH;
    float* cs2 = g_cs2 + f * BATCH;
    int t = threadIdx.x;
    int base = t * 8;

    float v1[8], v2[8];
    float s1 = 0.f, s2 = 0.f;
    #pragma unroll
    for (int i = 0; i < 8; i++) {
        float xv = p[base + i];
        s1 += xv;       v1[i] = s1;
        s2 += xv * xv;  v2[i] = s2;
    }
    __shared__ float sh1[1024], sh2[1024];
    sh1[t] = s1; sh2[t] = s2;
    __syncthreads();
    for (int off = 1; off < 1024; off <<= 1) {
        float a1 = (t >= off) ? sh1[t - off] : 0.f;
        float a2 = (t >= off) ? sh2[t - off] : 0.f;
        __syncthreads();
        sh1[t] += a1; sh2[t] += a2;
        __syncthreads();
    }
    float ex1 = (t > 0) ? sh1[t - 1] : 0.f;
    float ex2 = (t > 0) ? sh2[t - 1] : 0.f;
    #pragma unroll
    for (int i = 0; i < 8; i++) {
        cs [base + i] = v1[i] + ex1;
        cs2[base + i] = v2[i] + ex2;
    }
}

// -------------------- K4: est + linear + softmax, 32 samples/block ----------
#define FB 32
#define HCHUNK 512

__global__ __launch_bounds__(256) void final_kernel(
    const float* __restrict__ W_lin, const float* __restrict__ b_lin,
    float* __restrict__ out)
{
    __shared__ float sW[CLASSES][HCHUNK];   // 20 KB
    const int t = threadIdx.x;
    const int wid = t >> 5;
    const int lane = t & 31;
    const int b0 = blockIdx.x * FB + wid * 4;

    float acc[4][CLASSES];
    #pragma unroll
    for (int si = 0; si < 4; si++)
        #pragma unroll
        for (int c = 0; c < CLASSES; c++) acc[si][c] = 0.f;

    for (int ch = 0; ch < HIDDEN / HCHUNK; ch++) {
        int h0 = ch * HCHUNK;
        __syncthreads();
        for (int i = t; i < CLASSES * HCHUNK; i += 256) {
            int c = i / HCHUNK, h = i % HCHUNK;
            sW[c][h] = W_lin[c * LIN_IN + h0 + h];
        }
        __syncthreads();
        #pragma unroll 4
        for (int k = 0; k < HCHUNK / 32; k++) {
            int h = k * 32 + lane;
            float v[4];
            #pragma unroll
            for (int si = 0; si < 4; si++)
                v[si] = g_H[(size_t)(b0 + si) * HIDDEN + h0 + h];
            #pragma unroll
            for (int c = 0; c < CLASSES; c++) {
                float w = sW[c][h];
                #pragma unroll
                for (int si = 0; si < 4; si++)
                    acc[si][c] = fmaf(v[si], w, acc[si][c]);
            }
        }
    }

    for (int e = lane; e < EST_DIM; e += 32) {
        int f = e / 6;
        int r = e % 6;
        int j = r >> 1;
        int isvar = r & 1;
        int L = (j == 0) ? 32 : (j == 1) ? 128 : 512;
        float wv[CLASSES];
        #pragma unroll
        for (int c = 0; c < CLASSES; c++)
            wv[c] = W_lin[c * LIN_IN + HIDDEN + e];
        #pragma unroll
        for (int si = 0; si < 4; si++) {
            int b = b0 + si;
            float cnt = fminf((float)(b + 1), (float)L);
            float c1 = g_cs [f * BATCH + b];
            float c2 = g_cs2[f * BATCH + b];
            float p1 = (b >= L) ? g_cs [f * BATCH + b - L] : 0.f;
            float p2 = (b >= L) ? g_cs2[f * BATCH + b - L] : 0.f;
            float m = (c1 - p1) / cnt;
            float var = (c2 - p2) / cnt - m * m;
            float v = isvar ? var : m;
            #pragma unroll
            for (int c = 0; c < CLASSES; c++)
                acc[si][c] = fmaf(v, wv[c], acc[si][c]);
        }
    }

    #pragma unroll
    for (int si = 0; si < 4; si++)
        #pragma unroll
        for (int c = 0; c < CLASSES; c++) {
            float v = acc[si][c];
            #pragma unroll
            for (int off = 16; off; off >>= 1)
                v += __shfl_down_sync(0xffffffffu, v, off);
            acc[si][c] = v;
        }
    if (lane == 0) {
        #pragma unroll
        for (int si = 0; si < 4; si++) {
            float lg[CLASSES];
            float mx = -1e30f;
            #pragma unroll
            for (int c = 0; c < CLASSES; c++) {
                lg[c] = acc[si][c] + b_lin[c];
                mx = fmaxf(mx, lg[c]);
            }
            float sum = 0.f;
            #pragma unroll
            for (int c = 0; c < CLASSES; c++) { lg[c] = expf(lg[c] - mx); sum += lg[c]; }
            float inv = 1.f / sum;
            #pragma unroll
            for (int c = 0; c < CLASSES; c++)
                out[(b0 + si) * CLASSES + c] = lg[c] * inv;
        }
    }
}

// ---------------------------------------------------------------------------
// Launch. Inputs: x, W_ih, W_hh(unused), b_ih, b_hh, W_lin, b_lin
// ---------------------------------------------------------------------------
extern "C" void kernel_launch(void* const* d_in, const int* in_sizes, int n_in,
                              void* d_out, int out_size)
{
    const float* x     = (const float*)d_in[0];
    const float* W_ih  = (const float*)d_in[1];
    const float* b_ih  = (const float*)d_in[3];
    const float* b_hh  = (const float*)d_in[4];
    const float* W_lin = (const float*)d_in[5];
    const float* b_lin = (const float*)d_in[6];
    float* out = (float*)d_out;

    cudaFuncSetAttribute(gemm_mma_kernel,
                         cudaFuncAttributeMaxDynamicSharedMemorySize, SMEM_TOTAL);

    convert_x<<<(BATCH * INPUT / 4 + 255) / 256, 256>>>(x);
    convert_w<<<(HIDDEN * INPUT / 4 + 255) / 256, 256>>>(W_ih);
    gemm_mma_kernel<<<dim3(HIDDEN / BN, BATCH / BM), 256, SMEM_TOTAL>>>(b_ih, b_hh);
    pool_kernel<<<BATCH, 128>>>();
    scan_kernel<<<NUM_EH, 1024>>>();
    final_kernel<<<BATCH / FB, 256>>>(W_lin, b_lin, out);
}

// round 16
// speedup vs baseline: 5.5286x; 1.1062x over previous
#include <cuda_runtime.h>
#include <cuda_fp16.h>
#include <cstdint>

// Problem constants
#define BATCH   8192
#define INPUT   2048
#define HIDDEN  2048
#define CLASSES 10
#define KPOOL   45
#define NUM_EH  45
#define EST_DIM 270
#define LIN_IN  (HIDDEN + EST_DIM)   // 2318

// -------------------- scratch (device globals, no allocs) -------------------
// Only referenced from device code (GB300 ATS pitfall: passing these as host
// kernel args passes the host shadow address; device writes silently succeed).
__device__ float g_H[(size_t)BATCH * HIDDEN];
__device__ __half g_x_h[(size_t)BATCH * INPUT];
__device__ __half g_w_h[(size_t)HIDDEN * INPUT];
__device__ float g_pooledT[NUM_EH * BATCH];
__device__ float g_cs [NUM_EH * BATCH];
__device__ float g_cs2[NUM_EH * BATCH];

__device__ __forceinline__ uint32_t smem_u32(const void* p) {
    uint32_t a;
    asm("{ .reg .u64 t; cvta.to.shared.u64 t, %1; cvt.u32.u64 %0, t; }" : "=r"(a) : "l"(p));
    return a;
}

// ---------------- K0a: x fp32 -> fp16 ---------------------------------------
__global__ __launch_bounds__(256) void convert_x(const float* __restrict__ x)
{
    int i = blockIdx.x * blockDim.x + threadIdx.x;
    if (i >= BATCH * INPUT / 4) return;
    float4 v = ((const float4*)x)[i];
    ((__half2*)g_x_h)[i * 2 + 0] = __float22half2_rn(make_float2(v.x, v.y));
    ((__half2*)g_x_h)[i * 2 + 1] = __float22half2_rn(make_float2(v.z, v.w));
}

// ---------------- K0b: W fp32 -> fp16 ---------------------------------------
__global__ __launch_bounds__(256) void convert_w(const float* __restrict__ w)
{
    int i = blockIdx.x * blockDim.x + threadIdx.x;
    if (i >= HIDDEN * INPUT / 4) return;
    float4 v = ((const float4*)w)[i];
    ((__half2*)g_w_h)[i * 2 + 0] = __float22half2_rn(make_float2(v.x, v.y));
    ((__half2*)g_w_h)[i * 2 + 1] = __float22half2_rn(make_float2(v.z, v.w));
}

// -------------------- K1: mma.sync fp16 GEMM + bias + tanh ------------------
// C = tanh( x @ W^T + bias ), single fp16 term, K=2048.
// BM=128 x BN=128 x BK=32, 3-stage cp.async, 8 warps (4x2), warp 32x64.
// Fragments via NON-TRANS ldmatrix on padded-80B rows. B stored (n-rows,
// k-cols): non-trans gives lane = {two consecutive k at fixed n} — exactly
// the mma B fragment (R14's .trans gave the transposed fragment -> wrong).
#define BM 128
#define BN 128
#define KCHUNKS 64                  // 2048 / 32
#define ROW_B   80                  // 32 fp16 = 64B + 16B pad
#define TILE_B  (128 * ROW_B)       // 10240
#define STAGE_BYTES (2 * TILE_B)    // 20480
#define NSTAGE  3
#define SMEM_TOTAL (1024 + NSTAGE * STAGE_BYTES)   // 62464

__device__ __forceinline__ void mma_f16(float* c, const uint32_t* a, const uint32_t* b) {
    asm volatile(
        "mma.sync.aligned.m16n8k16.row.col.f32.f16.f16.f32 "
        "{%0,%1,%2,%3}, {%4,%5,%6,%7}, {%8,%9}, {%0,%1,%2,%3};"
        : "+f"(c[0]), "+f"(c[1]), "+f"(c[2]), "+f"(c[3])
        : "r"(a[0]), "r"(a[1]), "r"(a[2]), "r"(a[3]), "r"(b[0]), "r"(b[1]));
}

#define LDSM_X4(r0, r1, r2, r3, addr)                                          \
    asm volatile("ldmatrix.sync.aligned.m8n8.x4.shared.b16 {%0,%1,%2,%3}, [%4];" \
        : "=r"(r0), "=r"(r1), "=r"(r2), "=r"(r3) : "r"(addr))

__global__ __launch_bounds__(256, 2) void gemm_mma_kernel(
    const float* __restrict__ b_ih, const float* __restrict__ b_hh)
{
    extern __shared__ char smem[];
    float* s_bias = (float*)smem;
    const uint32_t s_tiles = smem_u32(smem) + 1024;

    const int tid = threadIdx.x;
    const int wid = tid >> 5;
    const int lane = tid & 31;
    const int bm = blockIdx.y * BM;
    const int bn = blockIdx.x * BN;
    const int warp_m = wid >> 1;
    const int warp_n = wid & 1;

    if (tid < BN) s_bias[tid] = b_ih[bn + tid] + b_hh[bn + tid];

    float c[2][8][4];
    #pragma unroll
    for (int i = 0; i < 2; i++)
        #pragma unroll
        for (int j = 0; j < 8; j++)
            #pragma unroll
            for (int q = 0; q < 4; q++) c[i][j][q] = 0.f;

    auto load_stage = [&](int chunk, int stage) {
        int k0 = chunk << 5;
        uint32_t sbase = s_tiles + stage * STAGE_BYTES;
        #pragma unroll
        for (int i = 0; i < 4; i++) {
            int g = tid + (i << 8);
            int isB = (i >= 2);
            int gg = g - (isB ? 512 : 0);
            int row = gg >> 2, c16 = gg & 3;
            const __half* src =
                (isB ? g_w_h + (size_t)(bn + row) * INPUT
                     : g_x_h + (size_t)(bm + row) * INPUT) + k0 + c16 * 8;
            uint32_t dst = sbase + (isB ? TILE_B : 0) + row * ROW_B + (c16 << 4);
            asm volatile("cp.async.cg.shared.global [%0], [%1], 16;"
                         :: "r"(dst), "l"(src));
        }
        asm volatile("cp.async.commit_group;" ::: "memory");
    };

    load_stage(0, 0);
    load_stage(1, 1);

    // ldmatrix per-lane address components (all non-trans)
    // A x4: m0=(rows0-7,k0-7) m1=(rows8-15,k0-7) m2=(rows0-7,k8-15) m3=(rows8-15,k8-15)
    const int a_row = lane & 15;
    const int a_col16 = (lane >> 4) << 4;
    // B x4: m0=(n0-7,k0-7) m1=(n0-7,k8-15) m2=(n8-15,k0-7) m3=(n8-15,k8-15)
    const int b_row = (lane & 7) + ((lane & 16) ? 8 : 0);
    const int b_col16 = (lane & 8) ? 16 : 0;

    for (int kt = 0; kt < KCHUNKS; kt++) {
        int s = kt % NSTAGE;
        if (kt + 2 < KCHUNKS)
            asm volatile("cp.async.wait_group 1;" ::: "memory");
        else
            asm volatile("cp.async.wait_group 0;" ::: "memory");
        __syncthreads();
        if (kt + 2 < KCHUNKS) load_stage(kt + 2, (kt + 2) % NSTAGE);

        uint32_t aBase = s_tiles + s * STAGE_BYTES;
        uint32_t bBase = aBase + TILE_B;

        #pragma unroll
        for (int k16 = 0; k16 < 2; k16++) {
            int kb = k16 * 32;
            uint32_t a[2][4];
            #pragma unroll
            for (int i = 0; i < 2; i++) {
                uint32_t addr = aBase
                    + (uint32_t)(warp_m * 32 + i * 16 + a_row) * ROW_B + kb + a_col16;
                LDSM_X4(a[i][0], a[i][1], a[i][2], a[i][3], addr);
            }
            uint32_t b[8][2];
            #pragma unroll
            for (int j2 = 0; j2 < 4; j2++) {
                uint32_t addr = bBase
                    + (uint32_t)(warp_n * 64 + j2 * 16 + b_row) * ROW_B + kb + b_col16;
                uint32_t t0, t1, t2, t3;
                LDSM_X4(t0, t1, t2, t3, addr);
                b[j2 * 2][0] = t0;     b[j2 * 2][1] = t1;
                b[j2 * 2 + 1][0] = t2; b[j2 * 2 + 1][1] = t3;
            }
            #pragma unroll
            for (int i = 0; i < 2; i++)
                #pragma unroll
                for (int j = 0; j < 8; j++)
                    mma_f16(c[i][j], a[i], b[j]);
        }
    }

    const int lr = lane >> 2;
    #pragma unroll
    for (int i = 0; i < 2; i++) {
        int r0 = bm + warp_m * 32 + i * 16 + lr;
        #pragma unroll
        for (int j = 0; j < 8; j++) {
            int ncol = warp_n * 64 + j * 8 + (lane & 3) * 2;
            float bia0 = s_bias[ncol], bia1 = s_bias[ncol + 1];
            float2 o0, o1;
            o0.x = tanhf(c[i][j][0] + bia0);
            o0.y = tanhf(c[i][j][1] + bia1);
            o1.x = tanhf(c[i][j][2] + bia0);
            o1.y = tanhf(c[i][j][3] + bia1);
            *(float2*)(g_H + (size_t)r0 * HIDDEN + bn + ncol) = o0;
            *(float2*)(g_H + (size_t)(r0 + 8) * HIDDEN + bn + ncol) = o1;
        }
    }
}

// -------------------- K2: avg-pool (45 windows of 45), transposed -----------
__global__ __launch_bounds__(128) void pool_kernel()
{
    int b = blockIdx.x;
    __shared__ float sh[2048];
    const float4* row = (const float4*)(g_H + (size_t)b * HIDDEN);
    #pragma unroll
    for (int i = 0; i < 4; i++) {
        int idx = threadIdx.x + i * 128;        // 512 float4 total
        ((float4*)sh)[idx] = row[idx];
    }
    __syncthreads();
    if (threadIdx.x < NUM_EH) {
        float s = 0.f;
        #pragma unroll
        for (int k = 0; k < KPOOL; k++) s += sh[threadIdx.x * KPOOL + k];
        g_pooledT[threadIdx.x * BATCH + b] = s * (1.0f / KPOOL);
    }
}

// -------------------- K3: per-feature prefix sums over batch ----------------
__global__ __launch_bounds__(1024) void scan_kernel()
{
    int f = blockIdx.x;
    const float* p = g_pooledT + f * BATCH;
    float* cs  = g_cs  + f * BATCH;
    float* cs2 = g_cs2 + f * BATCH;
    int t = threadIdx.x;
    int base = t * 8;

    float v1[8], v2[8];
    float s1 = 0.f, s2 = 0.f;
    #pragma unroll
    for (int i = 0; i < 8; i++) {
        float xv = p[base + i];
        s1 += xv;       v1[i] = s1;
        s2 += xv * xv;  v2[i] = s2;
    }
    __shared__ float sh1[1024], sh2[1024];
    sh1[t] = s1; sh2[t] = s2;
    __syncthreads();
    for (int off = 1; off < 1024; off <<= 1) {
        float a1 = (t >= off) ? sh1[t - off] : 0.f;
        float a2 = (t >= off) ? sh2[t - off] : 0.f;
        __syncthreads();
        sh1[t] += a1; sh2[t] += a2;
        __syncthreads();
    }
    float ex1 = (t > 0) ? sh1[t - 1] : 0.f;
    float ex2 = (t > 0) ? sh2[t - 1] : 0.f;
    #pragma unroll
    for (int i = 0; i < 8; i++) {
        cs [base + i] = v1[i] + ex1;
        cs2[base + i] = v2[i] + ex2;
    }
}

// -------------------- K4: est + linear + softmax, 32 samples/block ----------
#define FB 32
#define HCHUNK 512

__global__ __launch_bounds__(256) void final_kernel(
    const float* __restrict__ W_lin, const float* __restrict__ b_lin,
    float* __restrict__ out)
{
    __shared__ float sW[CLASSES][HCHUNK];   // 20 KB
    const int t = threadIdx.x;
    const int wid = t >> 5;
    const int lane = t & 31;
    const int b0 = blockIdx.x * FB + wid * 4;

    float acc[4][CLASSES];
    #pragma unroll
    for (int si = 0; si < 4; si++)
        #pragma unroll
        for (int c = 0; c < CLASSES; c++) acc[si][c] = 0.f;

    for (int ch = 0; ch < HIDDEN / HCHUNK; ch++) {
        int h0 = ch * HCHUNK;
        __syncthreads();
        for (int i = t; i < CLASSES * HCHUNK; i += 256) {
            int c = i / HCHUNK, h = i % HCHUNK;
            sW[c][h] = W_lin[c * LIN_IN + h0 + h];
        }
        __syncthreads();
        #pragma unroll 4
        for (int k = 0; k < HCHUNK / 32; k++) {
            int h = k * 32 + lane;
            float v[4];
            #pragma unroll
            for (int si = 0; si < 4; si++)
                v[si] = g_H[(size_t)(b0 + si) * HIDDEN + h0 + h];
            #pragma unroll
            for (int c = 0; c < CLASSES; c++) {
                float w = sW[c][h];
                #pragma unroll
                for (int si = 0; si < 4; si++)
                    acc[si][c] = fmaf(v[si], w, acc[si][c]);
            }
        }
    }

    for (int e = lane; e < EST_DIM; e += 32) {
        int f = e / 6;
        int r = e % 6;
        int j = r >> 1;
        int isvar = r & 1;
        int L = (j == 0) ? 32 : (j == 1) ? 128 : 512;
        float wv[CLASSES];
        #pragma unroll
        for (int c = 0; c < CLASSES; c++)
            wv[c] = W_lin[c * LIN_IN + HIDDEN + e];
        #pragma unroll
        for (int si = 0; si < 4; si++) {
            int b = b0 + si;
            float cnt = fminf((float)(b + 1), (float)L);
            float c1 = g_cs [f * BATCH + b];
            float c2 = g_cs2[f * BATCH + b];
            float p1 = (b >= L) ? g_cs [f * BATCH + b - L] : 0.f;
            float p2 = (b >= L) ? g_cs2[f * BATCH + b - L] : 0.f;
            float m = (c1 - p1) / cnt;
            float var = (c2 - p2) / cnt - m * m;
            float v = isvar ? var : m;
            #pragma unroll
            for (int c = 0; c < CLASSES; c++)
                acc[si][c] = fmaf(v, wv[c], acc[si][c]);
        }
    }

    #pragma unroll
    for (int si = 0; si < 4; si++)
        #pragma unroll
        for (int c = 0; c < CLASSES; c++) {
            float v = acc[si][c];
            #pragma unroll
            for (int off = 16; off; off >>= 1)
                v += __shfl_down_sync(0xffffffffu, v, off);
            acc[si][c] = v;
        }
    if (lane == 0) {
        #pragma unroll
        for (int si = 0; si < 4; si++) {
            float lg[CLASSES];
            float mx = -1e30f;
            #pragma unroll
            for (int c = 0; c < CLASSES; c++) {
                lg[c] = acc[si][c] + b_lin[c];
                mx = fmaxf(mx, lg[c]);
            }
            float sum = 0.f;
            #pragma unroll
            for (int c = 0; c < CLASSES; c++) { lg[c] = expf(lg[c] - mx); sum += lg[c]; }
            float inv = 1.f / sum;
            #pragma unroll
            for (int c = 0; c < CLASSES; c++)
                out[(b0 + si) * CLASSES + c] = lg[c] * inv;
        }
    }
}

// ---------------------------------------------------------------------------
// Launch. Inputs: x, W_ih, W_hh(unused), b_ih, b_hh, W_lin, b_lin
// ---------------------------------------------------------------------------
extern "C" void kernel_launch(void* const* d_in, const int* in_sizes, int n_in,
                              void* d_out, int out_size)
{
    const float* x     = (const float*)d_in[0];
    const float* W_ih  = (const float*)d_in[1];
    const float* b_ih  = (const float*)d_in[3];
    const float* b_hh  = (const float*)d_in[4];
    const float* W_lin = (const float*)d_in[5];
    const float* b_lin = (const float*)d_in[6];
    float* out = (float*)d_out;

    cudaFuncSetAttribute(gemm_mma_kernel,
                         cudaFuncAttributeMaxDynamicSharedMemorySize, SMEM_TOTAL);

    convert_x<<<(BATCH * INPUT / 4 + 255) / 256, 256>>>(x);
    convert_w<<<(HIDDEN * INPUT / 4 + 255) / 256, 256>>>(W_ih);
    gemm_mma_kernel<<<dim3(HIDDEN / BN, BATCH / BM), 256, SMEM_TOTAL>>>(b_ih, b_hh);
    pool_kernel<<<BATCH, 128>>>();
    scan_kernel<<<NUM_EH, 1024>>>();
    final_kernel<<<BATCH / FB, 256>>>(W_lin, b_lin, out);
}